// round 9
// baseline (speedup 1.0000x reference)
#include <cuda_runtime.h>

#define EPS 1e-8f

namespace {
constexpr int B = 256;
constexpr int S = 24;
constexpr int D = 256;
constexpr int N = 8192;
constexpr int T = 512;           // threads per block
constexpr int F4 = N / 4 / T;    // float4s per thread = 4
}

// ---------------------------------------------------------------------------
// Single fused kernel: grid = (S, B), 512 threads, 4 blocks/SM.
// Per warp: shuffle-build the member list for cluster i (no smem, no barrier).
// Main: new_patch_attn row (b,i). Tail (t<64): new_slots row (b,i).
// Block i==0, warp 0: slot_nums[b].
// ---------------------------------------------------------------------------
__global__ void __launch_bounds__(T, 4) fused_kernel(
    const float* __restrict__ slots,     // [B,S,D]
    const float* __restrict__ pa,        // [B,S,N]
    const int* __restrict__ clusters,    // [B,S] int32
    float* __restrict__ out_slots,       // [B,S,D]
    float* __restrict__ out_attn,        // [B,S,N]
    float* __restrict__ out_nums)        // [B]
{
    const int i = blockIdx.x;
    const int b = blockIdx.y;
    const int t = threadIdx.x;
    const int lane = t & 31;

    __shared__ float wsum[T / 32];

    // --- Per-warp packed-list build (lane l builds cluster l's list) ---
    int cl = -1;
    if (lane < S) cl = __ldg(&clusters[b * S + lane]);
    unsigned w0 = 0, w1 = 0, w2 = 0, w3 = 0;
    int m = 0;
    #pragma unroll
    for (int j = 0; j < S; j++) {
        int cj = __shfl_sync(0xFFFFFFFFu, cl, j);
        if (lane < S && cj == lane) {
            unsigned bit = (unsigned)j << (5 * (m % 6));
            switch (m / 6) { case 0: w0 |= bit; break; case 1: w1 |= bit; break;
                             case 2: w2 |= bit; break; default: w3 |= bit; }
            m++;
        }
    }
    if (lane < S) {
        for (int r = m; r < S; r++) {
            unsigned bit = 31u << (5 * (r % 6));
            switch (r / 6) { case 0: w0 |= bit; break; case 1: w1 |= bit; break;
                             case 2: w2 |= bit; break; default: w3 |= bit; }
        }
    }

    // slot_nums (once per batch)
    if (i == 0 && t < 32) {
        unsigned nz = __ballot_sync(0xFFFFFFFFu, (lane < S) && (m > 0));
        if (lane == 0) out_nums[b] = (float)__popc(nz);
    }

    // Broadcast cluster i's list to the whole warp
    unsigned wi[4];
    wi[0] = __shfl_sync(0xFFFFFFFFu, w0, i);
    wi[1] = __shfl_sync(0xFFFFFFFFu, w1, i);
    wi[2] = __shfl_sync(0xFFFFFFFFu, w2, i);
    wi[3] = __shfl_sync(0xFFFFFFFFu, w3, i);
    const int mi = __shfl_sync(0xFFFFFFFFu, m, i);

    // --- Attn accumulation ---
    const float4* base = (const float4*)pa + (size_t)b * (S * N / 4) + t;

    float4 acc[F4];
    #pragma unroll
    for (int k = 0; k < F4; k++) acc[k] = make_float4(EPS, EPS, EPS, EPS);

    #pragma unroll
    for (int r = 0; r < S; r++) {
        const int idx = (int)((wi[r / 6] >> (5 * (r % 6))) & 31u);
        if (idx >= S) break;   // sentinel
        const float4* row = base + idx * (N / 4);
        #pragma unroll
        for (int k = 0; k < F4; k++) {
            float4 v = __ldcs(row + k * T);
            acc[k].x += v.x; acc[k].y += v.y;
            acc[k].z += v.z; acc[k].w += v.w;
        }
    }

    // Row normalizer
    float ls = 0.0f;
    #pragma unroll
    for (int k = 0; k < F4; k++)
        ls += (acc[k].x + acc[k].y) + (acc[k].z + acc[k].w);
    #pragma unroll
    for (int off = 16; off > 0; off >>= 1)
        ls += __shfl_xor_sync(0xFFFFFFFFu, ls, off);
    if (lane == 0) wsum[t >> 5] = ls;
    __syncthreads();

    float tot = 0.0f;
    #pragma unroll
    for (int k = 0; k < T / 32; k++) tot += wsum[k];   // broadcast reads
    const float inv = 1.0f / tot;

    float4* o = (float4*)out_attn + (size_t)(b * S + i) * (N / 4) + t;
    #pragma unroll
    for (int k = 0; k < F4; k++) {
        float4 r = make_float4(acc[k].x * inv, acc[k].y * inv,
                               acc[k].z * inv, acc[k].w * inv);
        __stcs(o + k * T, r);
    }

    // --- Slots tail: threads 0..63 compute new_slots row (b,i) ---
    if (t < D / 4) {
        const float4* sb = (const float4*)slots + (size_t)b * (S * D / 4) + t;
        float4 sa = make_float4(0.f, 0.f, 0.f, 0.f);
        #pragma unroll
        for (int r = 0; r < S; r++) {
            const int idx = (int)((wi[r / 6] >> (5 * (r % 6))) & 31u);
            if (idx >= S) break;
            float4 v = __ldg(sb + idx * (D / 4));
            sa.x += v.x; sa.y += v.y; sa.z += v.z; sa.w += v.w;
        }
        const float sinv = 1.0f / ((float)mi + EPS);
        float4 r4 = make_float4(sa.x * sinv, sa.y * sinv, sa.z * sinv, sa.w * sinv);
        ((float4*)out_slots)[(size_t)(b * S + i) * (D / 4) + t] = r4;
    }
}

// ---------------------------------------------------------------------------
extern "C" void kernel_launch(void* const* d_in, const int* in_sizes, int n_in,
                              void* d_out, int out_size)
{
    const float* slots    = (const float*)d_in[0];   // [B,S,D]
    const float* pa       = (const float*)d_in[1];   // [B,S,N]
    const int*   clusters = (const int*)d_in[2];     // [B,S] int32

    float* out = (float*)d_out;
    float* out_slots = out;                              // [B,S,D]
    float* out_attn  = out + (size_t)B * S * D;          // [B,S,N]
    float* out_nums  = out_attn + (size_t)B * S * N;     // [B]

    fused_kernel<<<dim3(S, B), T>>>(slots, pa, clusters,
                                    out_slots, out_attn, out_nums);
}

// round 14
// speedup vs baseline: 1.6250x; 1.6250x over previous
#include <cuda_runtime.h>

#define EPS 1e-8f

namespace {
constexpr int B = 256;
constexpr int S = 24;
constexpr int D = 256;
constexpr int N = 8192;
constexpr int T = 512;           // threads per block (hot kernel)
constexpr int F4 = N / 4 / T;    // float4s per thread = 4
}

// Packed member lists: per (b,i), 24 x 5-bit slot indices (6 per 32-bit word),
// sentinel 31 terminates. 6144 * 16B = 96KB -> stays L2-resident.
__device__ uint4 g_packed[B * S];

// ---------------------------------------------------------------------------
// Pack kernel: member lists + slot_nums. 8 blocks x 1024 threads =
// 256 warps, one warp per batch, all resident in one wave.
// ---------------------------------------------------------------------------
__global__ void __launch_bounds__(1024) pack_kernel(
    const int* __restrict__ clusters,    // [B,S] int32
    float* __restrict__ out_nums)        // [B]
{
    const int b = (blockIdx.x * 1024 + threadIdx.x) >> 5;  // 0..255 = batch
    const int lane = threadIdx.x & 31;

    int cl = (lane < S) ? __ldg(&clusters[b * S + lane]) : -1;

    int m = 0;
    unsigned w[4] = {0u, 0u, 0u, 0u};
    #pragma unroll
    for (int j = 0; j < S; j++) {
        int cj = __shfl_sync(0xFFFFFFFFu, cl, j);
        if (lane < S && cj == lane) {
            w[m / 6] |= (unsigned)j << (5 * (m % 6));
            m++;
        }
    }
    if (lane < S) {
        for (int r = m; r < S; r++)
            w[r / 6] |= 31u << (5 * (r % 6));
        g_packed[b * S + lane] = make_uint4(w[0], w[1], w[2], w[3]);
    }

    unsigned nz = __ballot_sync(0xFFFFFFFFu, (lane < S) && (m > 0));
    if (lane == 0) out_nums[b] = (float)__popc(nz);
}

// ---------------------------------------------------------------------------
// Hot kernel: new_patch_attn row (b,i) + slots tail. grid = (S, B),
// 512 threads, 4 blocks/SM. One broadcast __ldg of the packed list.
// ---------------------------------------------------------------------------
__global__ void __launch_bounds__(T, 4) attn_kernel(
    const float* __restrict__ slots,     // [B,S,D]
    const float* __restrict__ pa,        // [B,S,N]
    float* __restrict__ out_slots,       // [B,S,D]
    float* __restrict__ out_attn)        // [B,S,N]
{
    const int i = blockIdx.x;
    const int b = blockIdx.y;
    const int t = threadIdx.x;

    __shared__ float wsum[T / 32];

    const uint4 pk = __ldg(&g_packed[b * S + i]);
    unsigned w[4] = {pk.x, pk.y, pk.z, pk.w};

    const float4* base = (const float4*)pa + (size_t)b * (S * N / 4) + t;

    float4 acc[F4];
    #pragma unroll
    for (int k = 0; k < F4; k++) acc[k] = make_float4(EPS, EPS, EPS, EPS);

    int m = 0;
    #pragma unroll
    for (int r = 0; r < S; r++) {
        const int idx = (int)((w[r / 6] >> (5 * (r % 6))) & 31u);
        if (idx >= S) break;   // sentinel: no more members
        m++;
        const float4* row = base + idx * (N / 4);
        #pragma unroll
        for (int k = 0; k < F4; k++) {
            float4 v = __ldcs(row + k * T);
            acc[k].x += v.x; acc[k].y += v.y;
            acc[k].z += v.z; acc[k].w += v.w;
        }
    }

    // Row normalizer
    float ls = 0.0f;
    #pragma unroll
    for (int k = 0; k < F4; k++)
        ls += (acc[k].x + acc[k].y) + (acc[k].z + acc[k].w);
    #pragma unroll
    for (int off = 16; off > 0; off >>= 1)
        ls += __shfl_xor_sync(0xFFFFFFFFu, ls, off);
    if ((t & 31) == 0) wsum[t >> 5] = ls;
    __syncthreads();

    float tot = 0.0f;
    #pragma unroll
    for (int k = 0; k < T / 32; k++) tot += wsum[k];   // broadcast reads
    const float inv = 1.0f / tot;

    float4* o = (float4*)out_attn + (size_t)(b * S + i) * (N / 4) + t;
    #pragma unroll
    for (int k = 0; k < F4; k++) {
        float4 r = make_float4(acc[k].x * inv, acc[k].y * inv,
                               acc[k].z * inv, acc[k].w * inv);
        __stcs(o + k * T, r);
    }

    // --- Slots tail: threads 0..63 compute new_slots row (b,i) ---
    if (t < D / 4) {
        const float4* sb = (const float4*)slots + (size_t)b * (S * D / 4) + t;
        float4 sa = make_float4(0.f, 0.f, 0.f, 0.f);
        #pragma unroll
        for (int r = 0; r < S; r++) {
            const int idx = (int)((w[r / 6] >> (5 * (r % 6))) & 31u);
            if (idx >= S) break;
            float4 v = __ldg(sb + idx * (D / 4));
            sa.x += v.x; sa.y += v.y; sa.z += v.z; sa.w += v.w;
        }
        const float sinv = 1.0f / ((float)m + EPS);
        float4 r4 = make_float4(sa.x * sinv, sa.y * sinv,
                                sa.z * sinv, sa.w * sinv);
        ((float4*)out_slots)[(size_t)(b * S + i) * (D / 4) + t] = r4;
    }
}

// ---------------------------------------------------------------------------
extern "C" void kernel_launch(void* const* d_in, const int* in_sizes, int n_in,
                              void* d_out, int out_size)
{
    const float* slots    = (const float*)d_in[0];   // [B,S,D]
    const float* pa       = (const float*)d_in[1];   // [B,S,N]
    const int*   clusters = (const int*)d_in[2];     // [B,S] int32

    float* out = (float*)d_out;
    float* out_slots = out;                              // [B,S,D]
    float* out_attn  = out + (size_t)B * S * D;          // [B,S,N]
    float* out_nums  = out_attn + (size_t)B * S * N;     // [B]

    pack_kernel<<<8, 1024>>>(clusters, out_nums);
    attn_kernel<<<dim3(S, B), T>>>(slots, pa, out_slots, out_attn);
}

// round 15
// speedup vs baseline: 1.6257x; 1.0004x over previous
#include <cuda_runtime.h>

#define EPS 1e-8f

namespace {
constexpr int B = 256;
constexpr int S = 24;
constexpr int D = 256;
constexpr int N = 8192;
constexpr int T = 512;           // threads per block (hot kernel)
constexpr int F4 = N / 4 / T;    // float4s per thread = 4
}

// Packed member lists: per (b,i), 24 x 5-bit slot indices (6 per 32-bit word),
// sentinel 31 terminates. 6144 * 16B = 96KB -> stays L2-resident.
__device__ uint4 g_packed[B * S];

// ---------------------------------------------------------------------------
// Pack kernel: member lists + slot_nums. 8 blocks x 1024 threads =
// 256 warps, one warp per batch, all resident in one wave.
// ---------------------------------------------------------------------------
__global__ void __launch_bounds__(1024) pack_kernel(
    const int* __restrict__ clusters,    // [B,S] int32
    float* __restrict__ out_nums)        // [B]
{
    const int b = (blockIdx.x * 1024 + threadIdx.x) >> 5;  // 0..255 = batch
    const int lane = threadIdx.x & 31;

    int cl = (lane < S) ? __ldg(&clusters[b * S + lane]) : -1;

    int m = 0;
    unsigned w[4] = {0u, 0u, 0u, 0u};
    #pragma unroll
    for (int j = 0; j < S; j++) {
        int cj = __shfl_sync(0xFFFFFFFFu, cl, j);
        if (lane < S && cj == lane) {
            w[m / 6] |= (unsigned)j << (5 * (m % 6));
            m++;
        }
    }
    if (lane < S) {
        for (int r = m; r < S; r++)
            w[r / 6] |= 31u << (5 * (r % 6));
        g_packed[b * S + lane] = make_uint4(w[0], w[1], w[2], w[3]);
    }

    unsigned nz = __ballot_sync(0xFFFFFFFFu, (lane < S) && (m > 0));
    if (lane == 0) out_nums[b] = (float)__popc(nz);
}

// ---------------------------------------------------------------------------
// Slots kernel: new_slots. grid = (S, B), 64 threads (one float4 per thread).
// ---------------------------------------------------------------------------
__global__ void __launch_bounds__(64) slots_kernel(
    const float* __restrict__ slots,     // [B,S,D]
    float* __restrict__ out_slots)       // [B,S,D]
{
    const int i = blockIdx.x;
    const int b = blockIdx.y;
    const int t = threadIdx.x;           // 0..63 -> float4 index in D

    const uint4 pk = __ldg(&g_packed[b * S + i]);
    unsigned w[4] = {pk.x, pk.y, pk.z, pk.w};

    const float4* base = (const float4*)slots + (size_t)b * (S * D / 4) + t;

    float4 acc = make_float4(0.f, 0.f, 0.f, 0.f);
    int m = 0;
    #pragma unroll
    for (int r = 0; r < S; r++) {
        const int idx = (int)((w[r / 6] >> (5 * (r % 6))) & 31u);
        if (idx >= S) break;
        float4 v = __ldg(base + idx * (D / 4));
        acc.x += v.x; acc.y += v.y; acc.z += v.z; acc.w += v.w;
        m++;
    }

    const float inv = 1.0f / ((float)m + EPS);
    float4 r4 = make_float4(acc.x * inv, acc.y * inv, acc.z * inv, acc.w * inv);
    ((float4*)out_slots)[(size_t)(b * S + i) * (D / 4) + t] = r4;
}

// ---------------------------------------------------------------------------
// Hot kernel: new_patch_attn. grid = (S, B), 512 threads, 4 blocks/SM.
// One broadcast __ldg of the packed list, then straight into row loads.
// ---------------------------------------------------------------------------
__global__ void __launch_bounds__(T, 4) attn_kernel(
    const float* __restrict__ pa,        // [B,S,N]
    float* __restrict__ out_attn)        // [B,S,N]
{
    const int i = blockIdx.x;
    const int b = blockIdx.y;
    const int t = threadIdx.x;

    __shared__ float wsum[T / 32];

    const uint4 pk = __ldg(&g_packed[b * S + i]);
    unsigned w[4] = {pk.x, pk.y, pk.z, pk.w};

    const float4* base = (const float4*)pa + (size_t)b * (S * N / 4) + t;

    float4 acc[F4];
    #pragma unroll
    for (int k = 0; k < F4; k++) acc[k] = make_float4(EPS, EPS, EPS, EPS);

    #pragma unroll
    for (int r = 0; r < S; r++) {
        const int idx = (int)((w[r / 6] >> (5 * (r % 6))) & 31u);
        if (idx >= S) break;   // sentinel: no more members
        const float4* row = base + idx * (N / 4);
        #pragma unroll
        for (int k = 0; k < F4; k++) {
            float4 v = __ldcs(row + k * T);
            acc[k].x += v.x; acc[k].y += v.y;
            acc[k].z += v.z; acc[k].w += v.w;
        }
    }

    // Row normalizer
    float ls = 0.0f;
    #pragma unroll
    for (int k = 0; k < F4; k++)
        ls += (acc[k].x + acc[k].y) + (acc[k].z + acc[k].w);
    #pragma unroll
    for (int off = 16; off > 0; off >>= 1)
        ls += __shfl_xor_sync(0xFFFFFFFFu, ls, off);
    if ((t & 31) == 0) wsum[t >> 5] = ls;
    __syncthreads();

    float tot = 0.0f;
    #pragma unroll
    for (int k = 0; k < T / 32; k++) tot += wsum[k];   // broadcast reads
    const float inv = 1.0f / tot;

    float4* o = (float4*)out_attn + (size_t)(b * S + i) * (N / 4) + t;
    #pragma unroll
    for (int k = 0; k < F4; k++) {
        float4 r = make_float4(acc[k].x * inv, acc[k].y * inv,
                               acc[k].z * inv, acc[k].w * inv);
        __stcs(o + k * T, r);
    }
}

// ---------------------------------------------------------------------------
extern "C" void kernel_launch(void* const* d_in, const int* in_sizes, int n_in,
                              void* d_out, int out_size)
{
    const float* slots    = (const float*)d_in[0];   // [B,S,D]
    const float* pa       = (const float*)d_in[1];   // [B,S,N]
    const int*   clusters = (const int*)d_in[2];     // [B,S] int32

    float* out = (float*)d_out;
    float* out_slots = out;                              // [B,S,D]
    float* out_attn  = out + (size_t)B * S * D;          // [B,S,N]
    float* out_nums  = out_attn + (size_t)B * S * N;     // [B]

    pack_kernel<<<8, 1024>>>(clusters, out_nums);
    slots_kernel<<<dim3(S, B), 64>>>(slots, out_slots);
    attn_kernel<<<dim3(S, B), T>>>(pa, out_attn);
}

// round 16
// speedup vs baseline: 1.8324x; 1.1272x over previous
#include <cuda_runtime.h>

#define EPS 1e-8f

namespace {
constexpr int B = 256;
constexpr int S = 24;
constexpr int D = 256;
constexpr int N = 8192;
constexpr int T = 512;           // threads per block
constexpr int F4 = N / 4 / T;    // float4s per thread = 4
}

// ---------------------------------------------------------------------------
// Single kernel: grid = (S+1, B), 512 threads, 4 blocks/SM.
//   i < S : new_patch_attn row (b,i). Member set = one warp ballot.
//   i == S: new_slots (24 rows, 3 passes of 8 rows) + slot_nums[b].
// ---------------------------------------------------------------------------
__global__ void __launch_bounds__(T, 4) fused_kernel(
    const float* __restrict__ slots,     // [B,S,D]
    const float* __restrict__ pa,        // [B,S,N]
    const int* __restrict__ clusters,    // [B,S] int32
    float* __restrict__ out_slots,       // [B,S,D]
    float* __restrict__ out_attn,        // [B,S,N]
    float* __restrict__ out_nums)        // [B]
{
    const int i = blockIdx.x;
    const int b = blockIdx.y;
    const int t = threadIdx.x;
    const int lane = t & 31;

    // Per-warp: each lane<S holds one cluster label (96B coalesced, L1/L2 hit)
    const int cl = (lane < S) ? __ldg(&clusters[b * S + lane]) : -1;

    if (i < S) {
        // ---------------- Attn path ----------------
        __shared__ float wsum[T / 32];

        unsigned mask = __ballot_sync(0xFFFFFFFFu, cl == i);  // member set

        const float4* base = (const float4*)pa + (size_t)b * (S * N / 4) + t;

        float4 acc[F4];
        #pragma unroll
        for (int k = 0; k < F4; k++) acc[k] = make_float4(EPS, EPS, EPS, EPS);

        unsigned mm = mask;
        while (mm) {
            const int idx = __ffs(mm) - 1;   // ascending j, matches ref order
            mm &= mm - 1;
            const float4* row = base + idx * (N / 4);
            #pragma unroll
            for (int k = 0; k < F4; k++) {
                float4 v = __ldcs(row + k * T);
                acc[k].x += v.x; acc[k].y += v.y;
                acc[k].z += v.z; acc[k].w += v.w;
            }
        }

        // Row normalizer
        float ls = 0.0f;
        #pragma unroll
        for (int k = 0; k < F4; k++)
            ls += (acc[k].x + acc[k].y) + (acc[k].z + acc[k].w);
        #pragma unroll
        for (int off = 16; off > 0; off >>= 1)
            ls += __shfl_xor_sync(0xFFFFFFFFu, ls, off);
        if (lane == 0) wsum[t >> 5] = ls;
        __syncthreads();

        float tot = 0.0f;
        #pragma unroll
        for (int k = 0; k < T / 32; k++) tot += wsum[k];   // broadcast reads
        const float inv = 1.0f / tot;

        float4* o = (float4*)out_attn + (size_t)(b * S + i) * (N / 4) + t;
        #pragma unroll
        for (int k = 0; k < F4; k++) {
            float4 r = make_float4(acc[k].x * inv, acc[k].y * inv,
                                   acc[k].z * inv, acc[k].w * inv);
            __stcs(o + k * T, r);
        }
    } else {
        // ---------------- Slots path (one block per batch) ----------------
        // 512 threads = 8 rows x 64 float4-lanes per pass, 3 passes.
        const float4* sb = (const float4*)slots + (size_t)b * (S * D / 4) + (t & 63);

        #pragma unroll
        for (int p = 0; p < 3; p++) {
            const int row = p * 8 + (t >> 6);                    // warp-uniform
            unsigned mask = __ballot_sync(0xFFFFFFFFu, cl == row);
            const int m = __popc(mask);

            float4 acc = make_float4(0.f, 0.f, 0.f, 0.f);
            while (mask) {
                const int idx = __ffs(mask) - 1;
                mask &= mask - 1;
                float4 v = __ldg(sb + idx * (D / 4));
                acc.x += v.x; acc.y += v.y; acc.z += v.z; acc.w += v.w;
            }
            const float inv = 1.0f / ((float)m + EPS);
            float4 r4 = make_float4(acc.x * inv, acc.y * inv,
                                    acc.z * inv, acc.w * inv);
            ((float4*)out_slots)[(size_t)(b * S + row) * (D / 4) + (t & 63)] = r4;
        }

        // slot_nums: OR-reduce of (1<<cl) across warp 0, then popcount.
        if (t < 32) {
            unsigned used = (lane < S) ? (1u << cl) : 0u;
            #pragma unroll
            for (int off = 16; off > 0; off >>= 1)
                used |= __shfl_xor_sync(0xFFFFFFFFu, used, off);
            if (lane == 0) out_nums[b] = (float)__popc(used);
        }
    }
}

// ---------------------------------------------------------------------------
extern "C" void kernel_launch(void* const* d_in, const int* in_sizes, int n_in,
                              void* d_out, int out_size)
{
    const float* slots    = (const float*)d_in[0];   // [B,S,D]
    const float* pa       = (const float*)d_in[1];   // [B,S,N]
    const int*   clusters = (const int*)d_in[2];     // [B,S] int32

    float* out = (float*)d_out;
    float* out_slots = out;                              // [B,S,D]
    float* out_attn  = out + (size_t)B * S * D;          // [B,S,N]
    float* out_nums  = out_attn + (size_t)B * S * N;     // [B]

    fused_kernel<<<dim3(S + 1, B), T>>>(slots, pa, clusters,
                                        out_slots, out_attn, out_nums);
}

// round 17
// speedup vs baseline: 1.8400x; 1.0041x over previous
#include <cuda_runtime.h>

#define EPS 1e-8f

namespace {
constexpr int B = 256;
constexpr int S = 24;
constexpr int D = 256;
constexpr int N = 8192;
constexpr int T = 512;           // threads per block
constexpr int F4 = N / 4 / T;    // float4s per thread = 4
}

// ---------------------------------------------------------------------------
// Single kernel: grid = (S+1, B), 512 threads, 4 blocks/SM.
//   i < S : new_patch_attn row (b,i). Member set = one warp ballot.
//           m==0 blocks short-circuit to a constant store (no loads, no
//           reduction, no barrier) — ~36% of blocks.
//   i == S: new_slots (24 rows, 3 passes of 8 rows) + slot_nums[b].
// ---------------------------------------------------------------------------
__global__ void __launch_bounds__(T, 4) fused_kernel(
    const float* __restrict__ slots,     // [B,S,D]
    const float* __restrict__ pa,        // [B,S,N]
    const int* __restrict__ clusters,    // [B,S] int32
    float* __restrict__ out_slots,       // [B,S,D]
    float* __restrict__ out_attn,        // [B,S,N]
    float* __restrict__ out_nums)        // [B]
{
    const int i = blockIdx.x;
    const int b = blockIdx.y;
    const int t = threadIdx.x;
    const int lane = t & 31;

    // Per-warp: each lane<S holds one cluster label (96B coalesced, L1/L2 hit)
    const int cl = (lane < S) ? __ldg(&clusters[b * S + lane]) : -1;

    if (i < S) {
        // ---------------- Attn path ----------------
        __shared__ float wsum[T / 32];

        const unsigned mask = __ballot_sync(0xFFFFFFFFu, cl == i);  // block-uniform

        float4* o = (float4*)out_attn + (size_t)(b * S + i) * (N / 4) + t;

        if (mask == 0u) {
            // Empty cluster: every element = EPS / (N*EPS) = 2^-13 exactly.
            const float c = EPS / ((float)N * EPS);
            const float4 r = make_float4(c, c, c, c);
            #pragma unroll
            for (int k = 0; k < F4; k++) __stcs(o + k * T, r);
            return;
        }

        const float4* base = (const float4*)pa + (size_t)b * (S * N / 4) + t;

        float4 acc[F4];
        #pragma unroll
        for (int k = 0; k < F4; k++) acc[k] = make_float4(EPS, EPS, EPS, EPS);

        unsigned mm = mask;
        while (mm) {
            const int idx = __ffs(mm) - 1;   // ascending j, matches ref order
            mm &= mm - 1;
            const float4* row = base + idx * (N / 4);
            #pragma unroll
            for (int k = 0; k < F4; k++) {
                float4 v = __ldcs(row + k * T);
                acc[k].x += v.x; acc[k].y += v.y;
                acc[k].z += v.z; acc[k].w += v.w;
            }
        }

        // Row normalizer
        float ls = 0.0f;
        #pragma unroll
        for (int k = 0; k < F4; k++)
            ls += (acc[k].x + acc[k].y) + (acc[k].z + acc[k].w);
        #pragma unroll
        for (int off = 16; off > 0; off >>= 1)
            ls += __shfl_xor_sync(0xFFFFFFFFu, ls, off);
        if (lane == 0) wsum[t >> 5] = ls;
        __syncthreads();

        float tot = 0.0f;
        #pragma unroll
        for (int k = 0; k < T / 32; k++) tot += wsum[k];   // broadcast reads
        const float inv = 1.0f / tot;

        #pragma unroll
        for (int k = 0; k < F4; k++) {
            float4 r = make_float4(acc[k].x * inv, acc[k].y * inv,
                                   acc[k].z * inv, acc[k].w * inv);
            __stcs(o + k * T, r);
        }
    } else {
        // ---------------- Slots path (one block per batch) ----------------
        // 512 threads = 8 rows x 64 float4-lanes per pass, 3 passes.
        const float4* sb = (const float4*)slots + (size_t)b * (S * D / 4) + (t & 63);

        #pragma unroll
        for (int p = 0; p < 3; p++) {
            const int row = p * 8 + (t >> 6);                    // warp-uniform
            unsigned mask = __ballot_sync(0xFFFFFFFFu, cl == row);
            const int m = __popc(mask);

            float4 acc = make_float4(0.f, 0.f, 0.f, 0.f);
            while (mask) {
                const int idx = __ffs(mask) - 1;
                mask &= mask - 1;
                float4 v = __ldg(sb + idx * (D / 4));
                acc.x += v.x; acc.y += v.y; acc.z += v.z; acc.w += v.w;
            }
            const float inv = 1.0f / ((float)m + EPS);
            float4 r4 = make_float4(acc.x * inv, acc.y * inv,
                                    acc.z * inv, acc.w * inv);
            ((float4*)out_slots)[(size_t)(b * S + row) * (D / 4) + (t & 63)] = r4;
        }

        // slot_nums: OR-reduce of (1<<cl) across warp 0, then popcount.
        if (t < 32) {
            unsigned used = (lane < S) ? (1u << cl) : 0u;
            #pragma unroll
            for (int off = 16; off > 0; off >>= 1)
                used |= __shfl_xor_sync(0xFFFFFFFFu, used, off);
            if (lane == 0) out_nums[b] = (float)__popc(used);
        }
    }
}

// ---------------------------------------------------------------------------
extern "C" void kernel_launch(void* const* d_in, const int* in_sizes, int n_in,
                              void* d_out, int out_size)
{
    const float* slots    = (const float*)d_in[0];   // [B,S,D]
    const float* pa       = (const float*)d_in[1];   // [B,S,N]
    const int*   clusters = (const int*)d_in[2];     // [B,S] int32

    float* out = (float*)d_out;
    float* out_slots = out;                              // [B,S,D]
    float* out_attn  = out + (size_t)B * S * D;          // [B,S,N]
    float* out_nums  = out_attn + (size_t)B * S * N;     // [B]

    fused_kernel<<<dim3(S + 1, B), T>>>(slots, pa, clusters,
                                        out_slots, out_attn, out_nums);
}